// round 5
// baseline (speedup 1.0000x reference)
#include <cuda_runtime.h>

// out[b, o] = max_i min(x[b, i], W[i, o])   (fuzzy max-min composition)
// x: [1024, 512] f32, W: [512, 512] f32, out: [1024, 512] f32.
//
// R5: sorted early-exit algorithm (exact, fp32):
//   sort x[b,:] descending -> (xs_j, perm_j). With G_j = prefix-max of
//   w[perm_j, o], out[b,o] = max_j min(xs_j, G_j); xs decreasing and G
//   increasing => stop at the first j with G_j >= xs_j.
//   Uniform data crosses at j ~ 23 (warp-max ~45 of 512) => ~11x less work
//   than the dense semiring GEMM, and the result is exact (rel_err = 0).
//
// One block per batch row b: 256 threads sort the row (bitonic, smem),
// then each thread produces outputs o = t and o = t + 256 with a shared
// warp-synchronous early-exit loop (W row reads coalesced per warp).

#define B_DIM 1024
#define IN_F  512
#define OUT_F 512
#define THREADS 256

__global__ __launch_bounds__(THREADS, 6)
void maxmin_sorted(const float* __restrict__ x,
                   const float* __restrict__ w,
                   float* __restrict__ out)
{
    __shared__ float skey[IN_F];
    __shared__ int   sidx[IN_F];

    const int t = threadIdx.x;
    const int b = blockIdx.x;

    // ---- load row b ----
    skey[t]           = x[b * IN_F + t];
    skey[t + THREADS] = x[b * IN_F + t + THREADS];
    sidx[t]           = t;
    sidx[t + THREADS] = t + THREADS;
    __syncthreads();

    // ---- bitonic sort ascending (key, idx), 512 elems / 256 threads ----
    for (int k = 2; k <= IN_F; k <<= 1) {
        for (int j = k >> 1; j > 0; j >>= 1) {
            // thread t owns pair (i, i|j) with bit j of i clear
            int i   = ((t & ~(j - 1)) << 1) | (t & (j - 1));
            int ixj = i | j;
            float a = skey[i], c = skey[ixj];
            bool asc = ((i & k) == 0);
            bool sw  = asc ? (a > c) : (a < c);
            if (sw) {
                skey[i] = c; skey[ixj] = a;
                int tmp = sidx[i]; sidx[i] = sidx[ixj]; sidx[ixj] = tmp;
            }
            __syncthreads();
        }
    }
    // descending view: j-th largest is skey[IN_F-1-j] / sidx[IN_F-1-j]

    // ---- early-exit scan: thread handles o = t and o = t + 256 ----
    const float* wc = w + t;         // column o = t; +256 for the second
    float g0 = 0.f, g1 = 0.f;        // prefix maxes (inputs >= 0)
    float best0 = 0.f, best1 = 0.f;

    for (int j = 0; j < IN_F; j += 4) {
        const int base = IN_F - 1 - j;
        float xs0 = skey[base],     xs1 = skey[base - 1];
        float xs2 = skey[base - 2], xs3 = skey[base - 3];
        int p0 = sidx[base],     p1 = sidx[base - 1];
        int p2 = sidx[base - 2], p3 = sidx[base - 3];

        // 8 independent coalesced loads (MLP=8) before the dependence chains
        float wa0 = wc[p0 * OUT_F],       wa1 = wc[p1 * OUT_F];
        float wa2 = wc[p2 * OUT_F],       wa3 = wc[p3 * OUT_F];
        float wb0 = wc[p0 * OUT_F + 256], wb1 = wc[p1 * OUT_F + 256];
        float wb2 = wc[p2 * OUT_F + 256], wb3 = wc[p3 * OUT_F + 256];

        g0 = fmaxf(g0, wa0); best0 = fmaxf(best0, fminf(xs0, g0));
        g1 = fmaxf(g1, wb0); best1 = fmaxf(best1, fminf(xs0, g1));
        g0 = fmaxf(g0, wa1); best0 = fmaxf(best0, fminf(xs1, g0));
        g1 = fmaxf(g1, wb1); best1 = fmaxf(best1, fminf(xs1, g1));
        g0 = fmaxf(g0, wa2); best0 = fmaxf(best0, fminf(xs2, g0));
        g1 = fmaxf(g1, wb2); best1 = fmaxf(best1, fminf(xs2, g1));
        g0 = fmaxf(g0, wa3); best0 = fmaxf(best0, fminf(xs3, g0));
        g1 = fmaxf(g1, wb3); best1 = fmaxf(best1, fminf(xs3, g1));

        // once g >= current xs, no later j can improve (xs only decreases)
        if (__all_sync(0xFFFFFFFFu, (g0 >= xs3) && (g1 >= xs3))) break;
    }

    out[b * OUT_F + t]       = best0;
    out[b * OUT_F + t + 256] = best1;
}

extern "C" void kernel_launch(void* const* d_in, const int* in_sizes, int n_in,
                              void* d_out, int out_size)
{
    const float* x = (const float*)d_in[0];   // [1024, 512]
    const float* w = (const float*)d_in[1];   // [512, 512]
    float* out = (float*)d_out;               // [1024, 512]

    maxmin_sorted<<<B_DIM, THREADS>>>(x, w, out);
}